// round 2
// baseline (speedup 1.0000x reference)
#include <cuda_runtime.h>
#include <math.h>

#define T    256
#define B    64
#define DIN  512
#define H    1024
#define DOUT 512
#define G4   (4*H)

// Persistent state (allocation-free scratch). h is double-buffered because
// every block reads ALL of h_prev while writing its slice of h_new.
// c is updated strictly in place by its owning thread.
__device__ float g_h0[2][B*H];
__device__ float g_c0[B*H];
__device__ float g_h1[2][B*H];
__device__ float g_c1[B*H];

__global__ void init_state()
{
    int i = blockIdx.x * blockDim.x + threadIdx.x;
    if (i < B*H) {
        g_h0[0][i] = 0.f;
        g_c0[i]    = 0.f;
        g_h1[0][i] = 0.f;
        g_c1[i]    = 0.f;
    }
}

// Fused gate GEMM + LSTM cell.
// Block tile: 32 batches x 16 hidden cols x 4 gates (2048 outputs, 8/thread).
// grid = (H/16, B/32) = (64, 2). 256 threads.
// K loop walks KX columns of (X, WX) then H columns of (Hprev, WH).
// layer==0: X = inputs slice [B, DIN], state = (h0, c0)
// layer==1: X = g_h0[wp] (just-written h0), state = (h1, c1)
__global__ __launch_bounds__(256) void lstm_gate_kernel(
    int layer, int rp,
    const float* __restrict__ Xext,   // inputs + t*B*DIN (layer 0 only)
    const float* __restrict__ WX,     // [KX, 4H]
    const float* __restrict__ WH,     // [H, 4H]
    const float* __restrict__ bias)   // [4H]
{
    __shared__ float As[32][33];      // [k][b] activations (padded: conflict-free)
    __shared__ float Ws[32][64];      // [k][g*16 + j] weights

    const int tid = threadIdx.x;
    const int tx  = tid & 15;         // hidden col within tile
    const int ty  = tid >> 4;         // batch pair index (2 batches each)
    const int n0  = blockIdx.x * 16;
    const int bt0 = blockIdx.y * 32;
    const int n   = n0 + tx;

    const int wp = rp ^ 1;
    const float* X;  int KX, ldx;
    const float* Hp; float* cptr; float* hout;
    if (layer == 0) {
        X = Xext;      KX = DIN; ldx = DIN;
        Hp = g_h0[rp]; cptr = g_c0; hout = g_h0[wp];
    } else {
        X = g_h0[wp];  KX = H;   ldx = H;
        Hp = g_h1[rp]; cptr = g_c1; hout = g_h1[wp];
    }

    float acc[4][2];
    #pragma unroll
    for (int g = 0; g < 4; ++g) { acc[g][0] = 0.f; acc[g][1] = 0.f; }

    const int KTOT = KX + H;
    for (int kc = 0; kc < KTOT; kc += 32) {
        // ---- stage activations As[k][b] (1024 floats, float4/thread) ----
        {
            int f  = tid;
            int b  = f >> 3;            // 0..31
            int k4 = (f & 7) * 4;       // 0,4,...,28
            int kk = kc + k4;
            float4 v;
            if (kk < KX) {
                v = *reinterpret_cast<const float4*>(X + (bt0 + b) * ldx + kk);
            } else {
                v = *reinterpret_cast<const float4*>(Hp + (bt0 + b) * H + (kk - KX));
            }
            As[k4+0][b] = v.x; As[k4+1][b] = v.y;
            As[k4+2][b] = v.z; As[k4+3][b] = v.w;
        }
        // ---- stage weights Ws[k][g*16+j] (2048 floats, 2x float4/thread) ----
        {
            const float* W  = (kc < KX) ? WX : WH;
            int krow        = (kc < KX) ? kc : (kc - KX);
            #pragma unroll
            for (int q = 0; q < 2; ++q) {
                int f   = tid + q * 256;     // 0..511 float4 segments
                int k   = f >> 4;            // 0..31
                int rem = f & 15;
                int g   = rem >> 2;          // gate
                int j4  = (rem & 3) * 4;     // col offset
                float4 v = *reinterpret_cast<const float4*>(
                    W + (size_t)(krow + k) * G4 + g * H + n0 + j4);
                Ws[k][g*16 + j4 + 0] = v.x;
                Ws[k][g*16 + j4 + 1] = v.y;
                Ws[k][g*16 + j4 + 2] = v.z;
                Ws[k][g*16 + j4 + 3] = v.w;
            }
        }
        __syncthreads();
        #pragma unroll
        for (int k = 0; k < 32; ++k) {
            float a0 = As[k][ty*2 + 0];
            float a1 = As[k][ty*2 + 1];
            float w0 = Ws[k][ 0 + tx];
            float w1 = Ws[k][16 + tx];
            float w2 = Ws[k][32 + tx];
            float w3 = Ws[k][48 + tx];
            acc[0][0] += a0*w0; acc[0][1] += a1*w0;
            acc[1][0] += a0*w1; acc[1][1] += a1*w1;
            acc[2][0] += a0*w2; acc[2][1] += a1*w2;
            acc[3][0] += a0*w3; acc[3][1] += a1*w3;
        }
        __syncthreads();
    }

    // ---- LSTM cell (gate order: i, f, c_hat, o) ----
    float bi = bias[0*H + n];
    float bf = bias[1*H + n];
    float bc = bias[2*H + n];
    float bo = bias[3*H + n];
    #pragma unroll
    for (int r = 0; r < 2; ++r) {
        int b = bt0 + ty*2 + r;
        float gi = acc[0][r] + bi;
        float gf = acc[1][r] + bf;
        float gc = acc[2][r] + bc;
        float go = acc[3][r] + bo;
        float si = 1.f / (1.f + __expf(-gi));
        float sf = 1.f / (1.f + __expf(-gf));
        float so = 1.f / (1.f + __expf(-go));
        float cv = sf * cptr[b*H + n] + si * tanhf(gc);
        cptr[b*H + n] = cv;
        hout[b*H + n] = so * tanhf(cv);
    }
}

// Output projection: outs[t] = h1_new @ Wout + bout.  [64,1024]@[1024,512]
// Block tile: 16 batches x 32 d-cols. grid = (DOUT/32, B/16) = (16, 4).
__global__ __launch_bounds__(256) void out_proj_kernel(
    int wp,
    const float* __restrict__ Wout,   // [H, DOUT]
    const float* __restrict__ bout,   // [DOUT]
    float* __restrict__ out_t)        // d_out + t*B*DOUT
{
    __shared__ float Hs[32][17];      // [k][b], padded
    __shared__ float Ws[32][32];      // [k][d]

    const int tid = threadIdx.x;
    const int tx  = tid & 15;         // 2 d-cols each
    const int ty  = tid >> 4;         // 1 batch each
    const int d0  = blockIdx.x * 32;
    const int bt0 = blockIdx.y * 16;
    const float* h1 = g_h1[wp];

    float acc0 = 0.f, acc1 = 0.f;

    for (int kc = 0; kc < H; kc += 32) {
        {   // stage acts: 512 floats, float2/thread along k
            int b  = tid >> 4;          // 0..15
            int k2 = (tid & 15) * 2;    // 0,2,...,30
            float2 v = *reinterpret_cast<const float2*>(h1 + (bt0 + b) * H + kc + k2);
            Hs[k2+0][b] = v.x;
            Hs[k2+1][b] = v.y;
        }
        {   // stage weights: 1024 floats, float4/thread along d
            int k  = tid >> 3;          // 0..31
            int d4 = (tid & 7) * 4;     // 0..28
            float4 v = *reinterpret_cast<const float4*>(
                Wout + (size_t)(kc + k) * DOUT + d0 + d4);
            Ws[k][d4+0] = v.x; Ws[k][d4+1] = v.y;
            Ws[k][d4+2] = v.z; Ws[k][d4+3] = v.w;
        }
        __syncthreads();
        #pragma unroll
        for (int k = 0; k < 32; ++k) {
            float a  = Hs[k][ty];
            float w0 = Ws[k][tx*2 + 0];
            float w1 = Ws[k][tx*2 + 1];
            acc0 += a*w0;
            acc1 += a*w1;
        }
        __syncthreads();
    }

    int b = bt0 + ty;
    int d = d0 + tx*2;
    out_t[b*DOUT + d + 0] = acc0 + bout[d + 0];
    out_t[b*DOUT + d + 1] = acc1 + bout[d + 1];
}

__global__ void final_copy(float* __restrict__ dst)
{
    int i = blockIdx.x * blockDim.x + threadIdx.x;
    if (i < B*H) {
        dst[i]       = g_h1[T & 1][i];   // final_h (T even -> buffer 0)
        dst[B*H + i] = g_c1[i];          // final_c
    }
}

extern "C" void kernel_launch(void* const* d_in, const int* in_sizes, int n_in,
                              void* d_out, int out_size)
{
    const float* inputs = (const float*)d_in[0];
    const float* Wx0    = (const float*)d_in[1];
    const float* Wh0    = (const float*)d_in[2];
    const float* b0     = (const float*)d_in[3];
    const float* Wx1    = (const float*)d_in[4];
    const float* Wh1    = (const float*)d_in[5];
    const float* b1     = (const float*)d_in[6];
    const float* Wout   = (const float*)d_in[7];
    const float* bout   = (const float*)d_in[8];
    float* out = (float*)d_out;

    init_state<<<(B*H + 255) / 256, 256>>>();

    dim3 gGate(H/16, B/32);     // 64 x 2 = 128 blocks
    dim3 gOut(DOUT/32, B/16);   // 16 x 4 = 64 blocks

    for (int t = 0; t < T; ++t) {
        int rp = t & 1;
        int wp = rp ^ 1;
        lstm_gate_kernel<<<gGate, 256>>>(0, rp, inputs + (size_t)t * B * DIN,
                                         Wx0, Wh0, b0);
        lstm_gate_kernel<<<gGate, 256>>>(1, rp, nullptr,
                                         Wx1, Wh1, b1);
        out_proj_kernel<<<gOut, 256>>>(wp, Wout, bout,
                                       out + (size_t)t * B * DOUT);
    }

    final_copy<<<(B*H + 255) / 256, 256>>>(out + (size_t)T * B * DOUT);
}

// round 3
// speedup vs baseline: 1.3821x; 1.3821x over previous
#include <cuda_runtime.h>
#include <math.h>

#define T_STEPS 256
#define B     64
#define DIN   512
#define H     1024
#define DOUT  512
#define G4    4096
#define NBLK  144
#define NTHR  256
#define LDA   68      // padded smem row stride (floats): 16B-aligned rows, low STS conflicts
#define LDGS  66      // Gs row stride: 8B-aligned, conflict-free gate reads

// ---------------- persistent state (allocation-free) ----------------
__device__ float g_h0[2][B*H];
__device__ float g_c0[B*H];
__device__ float g_h1[2][B*H];
__device__ float g_c1[B*H];

__device__ volatile unsigned g_gen;
__device__ unsigned          g_cnt;

__device__ __forceinline__ void grid_sync()
{
    __syncthreads();
    if (threadIdx.x == 0) {
        __threadfence();
        unsigned g = g_gen;
        if (atomicAdd(&g_cnt, 1u) == NBLK - 1u) {
            g_cnt = 0u;
            __threadfence();
            g_gen = g + 1u;
        } else {
            while (g_gen == g) { __nanosleep(40); }
        }
        __threadfence();
    }
    __syncthreads();
}

// packed dual-FMA: d.lo += a.lo*b.lo ; d.hi += a.hi*b.hi
#define FMA2(d, a, b) asm("fma.rn.f32x2 %0, %1, %2, %0;" : "+l"(d) : "l"(a), "l"(b))

__device__ __forceinline__ float lo32(unsigned long long v){ return __uint_as_float((unsigned)v); }
__device__ __forceinline__ float hi32(unsigned long long v){ return __uint_as_float((unsigned)(v >> 32)); }

struct Pref { float4 a0, a1, w; };

// ---- stage registers -> shared.  As[k][b]; Wd[k][2c+{0,1}] = dup(W col c) ----
__device__ __forceinline__ void stage_st(const Pref& p, float (*A)[LDA], float (*W)[LDA],
                                         int tid, int c0)
{
    {
        int f = tid;            int b = f >> 3, k4 = (f & 7) * 4;
        A[k4+0][b] = p.a0.x; A[k4+1][b] = p.a0.y;
        A[k4+2][b] = p.a0.z; A[k4+3][b] = p.a0.w;
    }
    {
        int f = tid + NTHR;     int b = f >> 3, k4 = (f & 7) * 4;
        A[k4+0][b] = p.a1.x; A[k4+1][b] = p.a1.y;
        A[k4+2][b] = p.a1.z; A[k4+3][b] = p.a1.w;
    }
    {
        int k = tid >> 3;
        float4 d0 = make_float4(p.w.x, p.w.x, p.w.y, p.w.y);
        float4 d1 = make_float4(p.w.z, p.w.z, p.w.w, p.w.w);
        *reinterpret_cast<float4*>(&W[k][2*c0    ]) = d0;
        *reinterpret_cast<float4*>(&W[k][2*c0 + 4]) = d1;
    }
}

// ---- 32-deep k-chunk: 2 LDS.128 + 4 FFMA2 per k per thread ----
__device__ __forceinline__ void mm_chunk(const float (*A)[LDA], const float (*W)[LDA],
                                         int tx, int ty,
                                         unsigned long long& a00, unsigned long long& a01,
                                         unsigned long long& a10, unsigned long long& a11)
{
    #pragma unroll
    for (int k = 0; k < 32; ++k) {
        ulonglong2 av = *reinterpret_cast<const ulonglong2*>(&A[k][4*ty]);
        ulonglong2 wv = *reinterpret_cast<const ulonglong2*>(&W[k][4*tx]);
        FMA2(a00, av.x, wv.x);
        FMA2(a01, av.x, wv.y);
        FMA2(a10, av.y, wv.x);
        FMA2(a11, av.y, wv.y);
    }
}

// ---- prefetch loads for gate GEMM (K = KX of X then H of Hp; W = WX then WH) ----
__device__ __forceinline__ void gate_ld(Pref& p, int kc, int KX,
        const float* __restrict__ X, int ldx,
        const float* __restrict__ Hp,
        const float* __restrict__ WX,
        const float* __restrict__ WH,
        int hid0, int tid)
{
    bool inX = (kc < KX);
    {
        int f = tid;        int b = f >> 3, k4 = (f & 7) * 4;
        p.a0 = inX ? *reinterpret_cast<const float4*>(X  + (size_t)b*ldx + kc + k4)
                   : *reinterpret_cast<const float4*>(Hp + (size_t)b*H   + (kc - KX) + k4);
    }
    {
        int f = tid + NTHR; int b = f >> 3, k4 = (f & 7) * 4;
        p.a1 = inX ? *reinterpret_cast<const float4*>(X  + (size_t)b*ldx + kc + k4)
                   : *reinterpret_cast<const float4*>(Hp + (size_t)b*H   + (kc - KX) + k4);
    }
    {
        int k = tid >> 3, rem = tid & 7, g = rem >> 1, j4 = (rem & 1) * 4;
        const float* Wp = inX ? WX : WH;
        int krow        = inX ? kc : kc - KX;
        p.w = *reinterpret_cast<const float4*>(Wp + (size_t)(krow + k) * G4 + g*H + hid0 + j4);
    }
}

__device__ __forceinline__ void proj_ld(Pref& p, int kc,
        const float* __restrict__ h1,
        const float* __restrict__ Wout,
        int col0, int tid)
{
    {
        int f = tid;        int b = f >> 3, k4 = (f & 7) * 4;
        p.a0 = *reinterpret_cast<const float4*>(h1 + (size_t)b*H + kc + k4);
    }
    {
        int f = tid + NTHR; int b = f >> 3, k4 = (f & 7) * 4;
        p.a1 = *reinterpret_cast<const float4*>(h1 + (size_t)b*H + kc + k4);
    }
    {
        int k = tid >> 3, j4 = (tid & 7) * 4;
        p.w = *reinterpret_cast<const float4*>(Wout + (size_t)(kc + k) * DOUT + col0 + j4);
    }
}

// ---- gate GEMM (64 x 32 gate-cols: 8 hidden x 4 gates) + fused LSTM cell ----
__device__ void do_gate(int layer, int rp,
        const float* __restrict__ Xin,      // layer 0: inputs + t*B*DIN
        const float* __restrict__ WX,
        const float* __restrict__ WH,
        const float* __restrict__ bias,
        int gb,
        float (*AsB)[32][LDA], float (*WdB)[32][LDA], float (*Gs)[LDGS])
{
    const int tid = threadIdx.x;
    const int tx  = tid & 15;          // col-pair (2 cols)
    const int ty  = tid >> 4;          // batch-quad (4 batches)
    const int hid0 = gb * 8;
    const int wp = rp ^ 1;

    const float* X;  int KX, ldx;
    const float* Hp; float* cptr; float* hout;
    if (layer == 0) { X = Xin;      KX = DIN; ldx = DIN; Hp = g_h0[rp]; cptr = g_c0; hout = g_h0[wp]; }
    else            { X = g_h0[wp]; KX = H;   ldx = H;   Hp = g_h1[rp]; cptr = g_c1; hout = g_h1[wp]; }

    const int rem = tid & 7;
    const int c0  = (rem >> 1) * 8 + (rem & 1) * 4;   // gate*8 + j4

    unsigned long long a00 = 0ull, a01 = 0ull, a10 = 0ull, a11 = 0ull;
    const int nc = (KX + H) / 32;

    Pref p;
    gate_ld(p, 0, KX, X, ldx, Hp, WX, WH, hid0, tid);
    stage_st(p, AsB[0], WdB[0], tid, c0);
    __syncthreads();

    for (int c = 0; c < nc; ++c) {
        int  cur  = c & 1;
        bool more = (c + 1 < nc);
        if (more) gate_ld(p, (c+1)*32, KX, X, ldx, Hp, WX, WH, hid0, tid);
        mm_chunk(AsB[cur], WdB[cur], tx, ty, a00, a01, a10, a11);
        if (more) stage_st(p, AsB[cur^1], WdB[cur^1], tid, c0);
        __syncthreads();
    }

    // park pre-activations in shared, then fused cell
    *reinterpret_cast<unsigned long long*>(&Gs[2*tx  ][4*ty  ]) = a00;
    *reinterpret_cast<unsigned long long*>(&Gs[2*tx+1][4*ty  ]) = a01;
    *reinterpret_cast<unsigned long long*>(&Gs[2*tx  ][4*ty+2]) = a10;
    *reinterpret_cast<unsigned long long*>(&Gs[2*tx+1][4*ty+2]) = a11;
    __syncthreads();

    #pragma unroll
    for (int j = 0; j < 2; ++j) {
        int item = tid + j * NTHR;        // 512 (b, hid) pairs
        int b   = item >> 3;
        int hid = item & 7;
        int n   = hid0 + hid;
        float gi = Gs[0*8 + hid][b] + bias[0*H + n];
        float gf = Gs[1*8 + hid][b] + bias[1*H + n];
        float gc = Gs[2*8 + hid][b] + bias[2*H + n];
        float go = Gs[3*8 + hid][b] + bias[3*H + n];
        float si = 1.f / (1.f + __expf(-gi));
        float sf = 1.f / (1.f + __expf(-gf));
        float so = 1.f / (1.f + __expf(-go));
        int idx = b * H + n;
        float cv = sf * cptr[idx] + si * tanhf(gc);
        cptr[idx] = cv;
        hout[idx] = so * tanhf(cv);
    }
}

// ---- output projection tile (64 x 32 cols), K = H ----
__device__ void do_proj(int pb, int tprev,
        const float* __restrict__ Wout, const float* __restrict__ bout,
        float* __restrict__ out,
        float (*AsB)[32][LDA], float (*WdB)[32][LDA])
{
    const int tid = threadIdx.x;
    const int tx  = tid & 15;
    const int ty  = tid >> 4;
    const int col0 = pb * 32;
    const float* h1 = g_h1[(tprev & 1) ^ 1];
    const int c0 = (tid & 7) * 4;

    unsigned long long a00 = 0ull, a01 = 0ull, a10 = 0ull, a11 = 0ull;
    const int nc = H / 32;

    Pref p;
    proj_ld(p, 0, h1, Wout, col0, tid);
    stage_st(p, AsB[0], WdB[0], tid, c0);
    __syncthreads();

    for (int c = 0; c < nc; ++c) {
        int  cur  = c & 1;
        bool more = (c + 1 < nc);
        if (more) proj_ld(p, (c+1)*32, h1, Wout, col0, tid);
        mm_chunk(AsB[cur], WdB[cur], tx, ty, a00, a01, a10, a11);
        if (more) stage_st(p, AsB[cur^1], WdB[cur^1], tid, c0);
        __syncthreads();
    }

    float* o  = out + (size_t)tprev * B * DOUT;
    int cc = col0 + 2 * tx;
    float bo0 = bout[cc], bo1 = bout[cc + 1];
    int b0 = 4 * ty;
    o[(b0+0)*DOUT + cc    ] = lo32(a00) + bo0;
    o[(b0+1)*DOUT + cc    ] = hi32(a00) + bo0;
    o[(b0+0)*DOUT + cc + 1] = lo32(a01) + bo1;
    o[(b0+1)*DOUT + cc + 1] = hi32(a01) + bo1;
    o[(b0+2)*DOUT + cc    ] = lo32(a10) + bo0;
    o[(b0+3)*DOUT + cc    ] = hi32(a10) + bo0;
    o[(b0+2)*DOUT + cc + 1] = lo32(a11) + bo1;
    o[(b0+3)*DOUT + cc + 1] = hi32(a11) + bo1;
}

__global__ __launch_bounds__(NTHR) void lstm_persistent(
    const float* __restrict__ inputs,
    const float* __restrict__ Wx0, const float* __restrict__ Wh0, const float* __restrict__ b0,
    const float* __restrict__ Wx1, const float* __restrict__ Wh1, const float* __restrict__ b1,
    const float* __restrict__ Wout, const float* __restrict__ bout,
    float* __restrict__ out)
{
    __shared__ __align__(16) float As[2][32][LDA];
    __shared__ __align__(16) float Wd[2][32][LDA];
    __shared__ __align__(16) float Gs[32][LDGS];

    const int bid = blockIdx.x;
    const int tid = threadIdx.x;

    // zero state
    for (int i = bid * NTHR + tid; i < B*H; i += NBLK * NTHR) {
        g_h0[0][i] = 0.f; g_h0[1][i] = 0.f; g_c0[i] = 0.f;
        g_h1[0][i] = 0.f; g_h1[1][i] = 0.f; g_c1[i] = 0.f;
    }
    grid_sync();

    for (int t = 0; t < T_STEPS; ++t) {
        int rp = t & 1;
        // ---- PHASE A: layer0 gate (blocks 0..127) + proj(t-1) (blocks 128..143) ----
        if (bid < 128) {
            do_gate(0, rp, inputs + (size_t)t * B * DIN, Wx0, Wh0, b0, bid, As, Wd, Gs);
        } else if (t > 0) {
            do_proj(bid - 128, t - 1, Wout, bout, out, As, Wd);
        }
        grid_sync();
        // ---- PHASE B: layer1 gate ----
        if (bid < 128) {
            do_gate(1, rp, nullptr, Wx1, Wh1, b1, bid, As, Wd, Gs);
        }
        grid_sync();
    }

    // tail: proj(T-1) + final (h, c) copy
    if (bid < 16) {
        do_proj(bid, T_STEPS - 1, Wout, bout, out, As, Wd);
    } else {
        float* dst = out + (size_t)T_STEPS * B * DOUT;
        for (int i = (bid - 16) * NTHR + tid; i < B*H; i += 128 * NTHR) {
            dst[i]       = g_h1[0][i];   // final h1 (step 255 wrote buffer 0)
            dst[B*H + i] = g_c1[i];
        }
    }
}

extern "C" void kernel_launch(void* const* d_in, const int* in_sizes, int n_in,
                              void* d_out, int out_size)
{
    const float* inputs = (const float*)d_in[0];
    const float* Wx0    = (const float*)d_in[1];
    const float* Wh0    = (const float*)d_in[2];
    const float* b0     = (const float*)d_in[3];
    const float* Wx1    = (const float*)d_in[4];
    const float* Wh1    = (const float*)d_in[5];
    const float* b1     = (const float*)d_in[6];
    const float* Wout   = (const float*)d_in[7];
    const float* bout   = (const float*)d_in[8];
    float* out = (float*)d_out;

    lstm_persistent<<<NBLK, NTHR>>>(inputs, Wx0, Wh0, b0, Wx1, Wh1, b1,
                                    Wout, bout, out);
}